// round 2
// baseline (speedup 1.0000x reference)
#include <cuda_runtime.h>
#include <math.h>

#define BB 4
#define SS 2048
#define DDIM 1024
#define HH 16
#define HDD 64
#define RR (BB*SS)          /* 8192 rows */

// ---------------- scratch (static device allocations; no cudaMalloc) --------
__device__ float g_h  [RR * DDIM];        // LN output (reused twice)     32 MB
__device__ float g_qkv[RR * 3 * DDIM];    // QKV                          96 MB
__device__ float g_ctx[RR * DDIM];        // attention context            32 MB
__device__ float g_mid[RR * 4 * DDIM];    // MLP hidden                  128 MB

// ---------------- LayerNorm: one block per row, 256 threads -----------------
__global__ __launch_bounds__(256) void ln_kernel(
    const float* __restrict__ x, const float* __restrict__ gw,
    const float* __restrict__ sw, float* __restrict__ out)
{
    int row = blockIdx.x;
    int tid = threadIdx.x;
    const float4* xr = (const float4*)(x + (size_t)row * DDIM);
    float4 xv = xr[tid];                      // 256 thr * 4 = 1024 elems
    float sum = xv.x + xv.y + xv.z + xv.w;
    float sq  = xv.x*xv.x + xv.y*xv.y + xv.z*xv.z + xv.w*xv.w;

    // warp reduce
    #pragma unroll
    for (int o = 16; o > 0; o >>= 1) {
        sum += __shfl_down_sync(0xffffffffu, sum, o);
        sq  += __shfl_down_sync(0xffffffffu, sq,  o);
    }
    __shared__ float rs[8], rq[8], bmean, brstd;
    int wid = tid >> 5, lid = tid & 31;
    if (lid == 0) { rs[wid] = sum; rq[wid] = sq; }
    __syncthreads();
    if (wid == 0) {
        float s2 = (lid < 8) ? rs[lid] : 0.f;
        float q2 = (lid < 8) ? rq[lid] : 0.f;
        #pragma unroll
        for (int o = 4; o > 0; o >>= 1) {
            s2 += __shfl_down_sync(0xffffffffu, s2, o);
            q2 += __shfl_down_sync(0xffffffffu, q2, o);
        }
        if (lid == 0) {
            float mean = s2 * (1.0f / DDIM);
            float var  = q2 * (1.0f / DDIM) - mean * mean;
            bmean = mean;
            brstd = rsqrtf(var + 1e-5f);
        }
    }
    __syncthreads();
    float mean = bmean, rstd = brstd;
    float4 gv = ((const float4*)gw)[tid];
    float4 sv = ((const float4*)sw)[tid];
    float4 o;
    o.x = gv.x * ((xv.x - mean) * rstd) + sv.x;
    o.y = gv.y * ((xv.y - mean) * rstd) + sv.y;
    o.z = gv.z * ((xv.z - mean) * rstd) + sv.z;
    o.w = gv.w * ((xv.w - mean) * rstd) + sv.w;
    ((float4*)(out + (size_t)row * DDIM))[tid] = o;
}

// ---------------- GELU (tanh) -----------------------------------------------
__device__ __forceinline__ float gelu_f(float v) {
    const float c = 0.7978845608028654f;
    float t = tanhf(c * (v + 0.044715f * v * v * v));
    return v * 0.5f * (1.0f + t);
}

// ---------------- Tiled SGEMM: C = act(A@B + bias) (+ res) ------------------
// A: [M,K] row-major, B: [K,N] row-major, 128x128 tile, BK=16, 256 threads.
template <bool BIAS, bool GELU, bool RES>
__global__ __launch_bounds__(256, 2) void gemm_kernel(
    const float* __restrict__ A, const float* __restrict__ Bm,
    const float* __restrict__ bias, const float* __restrict__ res,
    float* __restrict__ C, int M, int N, int K)
{
    __shared__ float As[16][128];   // transposed: As[k][m]
    __shared__ float Bs[16][128];   // Bs[k][n]

    int tid = threadIdx.x;
    int tx = tid & 15;              // col group (8 cols each)
    int ty = tid >> 4;              // row group (8 rows each)
    size_t row0 = (size_t)blockIdx.y * 128;
    int    col0 = blockIdx.x * 128;
    const float* Ab = A + row0 * K;
    const float* Bb = Bm + col0;

    float acc[8][8];
    #pragma unroll
    for (int i = 0; i < 8; i++)
        #pragma unroll
        for (int j = 0; j < 8; j++) acc[i][j] = 0.f;

    int aRow = tid >> 2;            // 0..63 (+64 second pass)
    int aC4  = tid & 3;
    int bRow = tid >> 5;            // 0..7  (+8 second pass)
    int bC4  = tid & 31;

    for (int k0 = 0; k0 < K; k0 += 16) {
        #pragma unroll
        for (int i = 0; i < 2; i++) {
            int r = aRow + i * 64;
            float4 a = *(const float4*)(Ab + (size_t)r * K + k0 + aC4 * 4);
            As[aC4*4+0][r] = a.x; As[aC4*4+1][r] = a.y;
            As[aC4*4+2][r] = a.z; As[aC4*4+3][r] = a.w;
        }
        #pragma unroll
        for (int i = 0; i < 2; i++) {
            int r = bRow + i * 8;
            *(float4*)&Bs[r][bC4*4] =
                *(const float4*)(Bb + (size_t)(k0 + r) * N + bC4 * 4);
        }
        __syncthreads();
        #pragma unroll
        for (int k = 0; k < 16; k++) {
            float ar[8], br[8];
            *(float4*)(ar)     = *(const float4*)&As[k][ty*8];
            *(float4*)(ar + 4) = *(const float4*)&As[k][ty*8 + 4];
            *(float4*)(br)     = *(const float4*)&Bs[k][tx*8];
            *(float4*)(br + 4) = *(const float4*)&Bs[k][tx*8 + 4];
            #pragma unroll
            for (int i = 0; i < 8; i++)
                #pragma unroll
                for (int j = 0; j < 8; j++)
                    acc[i][j] += ar[i] * br[j];
        }
        __syncthreads();
    }

    // epilogue
    #pragma unroll
    for (int i = 0; i < 8; i++) {
        size_t r = row0 + ty * 8 + i;
        #pragma unroll
        for (int j = 0; j < 8; j += 4) {
            int c = col0 + tx * 8 + j;
            float v0 = acc[i][j+0], v1 = acc[i][j+1], v2 = acc[i][j+2], v3 = acc[i][j+3];
            if (BIAS) {
                float4 bb = *(const float4*)(bias + c);
                v0 += bb.x; v1 += bb.y; v2 += bb.z; v3 += bb.w;
            }
            if (GELU) { v0 = gelu_f(v0); v1 = gelu_f(v1); v2 = gelu_f(v2); v3 = gelu_f(v3); }
            if (RES) {
                float4 rr = *(const float4*)(res + r * N + c);
                v0 += rr.x; v1 += rr.y; v2 += rr.z; v3 += rr.w;
            }
            float4 o; o.x = v0; o.y = v1; o.z = v2; o.w = v3;
            *(float4*)(C + r * N + c) = o;
        }
    }
}

// ---------------- Flash attention (fp32) ------------------------------------
// grid: (S/64, H, B), 64 threads; thread t owns query row qt*64+t.
// K/V tiles of 32 rows in SMEM; q + accumulator in registers.
__global__ __launch_bounds__(64) void attn_kernel(
    const float* __restrict__ qkv, float* __restrict__ ctx)
{
    int qt = blockIdx.x, h = blockIdx.y, b = blockIdx.z;
    int t  = threadIdx.x;
    int qrow = qt * 64 + t;

    __shared__ float Ks[32][64];
    __shared__ float Vs[32][64];
    __shared__ float Ss[64][33];

    float q[64], acc[64];
    const float scale = 0.125f;     // 1/sqrt(64)
    size_t qbase = ((size_t)b * SS + qrow) * 3 * DDIM + (size_t)h * 64;
    #pragma unroll
    for (int d = 0; d < 64; d += 4) {
        float4 qv = *(const float4*)(qkv + qbase + d);
        q[d+0] = qv.x * scale; q[d+1] = qv.y * scale;
        q[d+2] = qv.z * scale; q[d+3] = qv.w * scale;
        acc[d+0] = 0.f; acc[d+1] = 0.f; acc[d+2] = 0.f; acc[d+3] = 0.f;
    }

    float m = -INFINITY, l = 0.f;
    int ntiles = (qt * 64 + 63) / 32 + 1;      // 2*qt + 2

    for (int kt = 0; kt < ntiles; kt++) {
        int kbase = kt * 32;
        __syncthreads();
        // cooperative load K,V tiles (32x64 each): 512 float4, 8 per thread
        #pragma unroll
        for (int i = 0; i < 8; i++) {
            int fi = t + 64 * i;
            int r  = fi >> 4;
            int c4 = fi & 15;
            size_t kr = ((size_t)b * SS + kbase + r) * 3 * DDIM + DDIM + (size_t)h * 64;
            *(float4*)&Ks[r][c4*4] = *(const float4*)(qkv + kr + c4 * 4);
            *(float4*)&Vs[r][c4*4] = *(const float4*)(qkv + kr + DDIM + c4 * 4);
        }
        __syncthreads();

        int jmax = qrow - kbase + 1;           // #valid keys in this tile
        if (jmax > 32) jmax = 32;
        float tmax = -INFINITY;
        #pragma unroll 4
        for (int j = 0; j < 32; j++) {
            float s = 0.f;
            const float4* kr4 = (const float4*)Ks[j];
            #pragma unroll
            for (int d4 = 0; d4 < 16; d4++) {
                float4 kv = kr4[d4];
                s += q[4*d4+0]*kv.x + q[4*d4+1]*kv.y + q[4*d4+2]*kv.z + q[4*d4+3]*kv.w;
            }
            if (j >= jmax) s = -INFINITY;
            Ss[t][j] = s;
            tmax = fmaxf(tmax, s);
        }
        float mnew = fmaxf(m, tmax);           // finite after first tile
        float corr = expf(m - mnew);
        l *= corr;
        #pragma unroll
        for (int d = 0; d < 64; d++) acc[d] *= corr;
        #pragma unroll 2
        for (int j = 0; j < 32; j++) {
            float p = expf(Ss[t][j] - mnew);   // masked -> exp(-inf) = 0
            l += p;
            const float4* vr4 = (const float4*)Vs[j];
            #pragma unroll
            for (int d4 = 0; d4 < 16; d4++) {
                float4 vv = vr4[d4];
                acc[4*d4+0] += p * vv.x; acc[4*d4+1] += p * vv.y;
                acc[4*d4+2] += p * vv.z; acc[4*d4+3] += p * vv.w;
            }
        }
        m = mnew;
    }

    float inv = 1.f / l;
    size_t obase = ((size_t)b * SS + qrow) * DDIM + (size_t)h * 64;
    #pragma unroll
    for (int d = 0; d < 64; d += 4) {
        float4 o;
        o.x = acc[d+0]*inv; o.y = acc[d+1]*inv; o.z = acc[d+2]*inv; o.w = acc[d+3]*inv;
        *(float4*)(ctx + obase + d) = o;
    }
}

// ---------------- host launch ------------------------------------------------
extern "C" void kernel_launch(void* const* d_in, const int* in_sizes, int n_in,
                              void* d_out, int out_size)
{
    const float* x    = (const float*)d_in[0];
    const float* Wqkv = (const float*)d_in[1];
    const float* Wout = (const float*)d_in[2];
    const float* bout = (const float*)d_in[3];
    const float* W1   = (const float*)d_in[4];
    const float* b1   = (const float*)d_in[5];
    const float* W2   = (const float*)d_in[6];
    const float* b2   = (const float*)d_in[7];
    const float* g1   = (const float*)d_in[8];
    const float* s1   = (const float*)d_in[9];
    const float* g2   = (const float*)d_in[10];
    const float* s2   = (const float*)d_in[11];
    float* out = (float*)d_out;

    float *ph, *pqkv, *pctx, *pmid;
    cudaGetSymbolAddress((void**)&ph,   g_h);
    cudaGetSymbolAddress((void**)&pqkv, g_qkv);
    cudaGetSymbolAddress((void**)&pctx, g_ctx);
    cudaGetSymbolAddress((void**)&pmid, g_mid);

    // 1. LN1: x -> h
    ln_kernel<<<RR, 256>>>(x, g1, s1, ph);
    // 2. qkv = h @ Wqkv   [8192,1024]x[1024,3072]
    gemm_kernel<false,false,false><<<dim3(3*DDIM/128, RR/128), 256>>>(
        ph, Wqkv, nullptr, nullptr, pqkv, RR, 3*DDIM, DDIM);
    // 3. attention -> ctx
    attn_kernel<<<dim3(SS/64, HH, BB), 64>>>(pqkv, pctx);
    // 4. x1 = x + ctx @ Wout + bout   -> out
    gemm_kernel<true,false,true><<<dim3(DDIM/128, RR/128), 256>>>(
        pctx, Wout, bout, x, out, RR, DDIM, DDIM);
    // 5. LN2: out -> h
    ln_kernel<<<RR, 256>>>(out, g2, s2, ph);
    // 6. mid = gelu(h @ W1 + b1)   [8192,1024]x[1024,4096]
    gemm_kernel<true,true,false><<<dim3(4*DDIM/128, RR/128), 256>>>(
        ph, W1, b1, nullptr, pmid, RR, 4*DDIM, DDIM);
    // 7. out = out + mid @ W2 + b2  [8192,4096]x[4096,1024]
    gemm_kernel<true,false,true><<<dim3(DDIM/128, RR/128), 256>>>(
        pmid, W2, b2, out, out, RR, DDIM, 4*DDIM);
}

// round 4
// speedup vs baseline: 1.5894x; 1.5894x over previous
#include <cuda_runtime.h>
#include <cuda_bf16.h>
#include <math.h>
#include <stdint.h>

#define BB 4
#define SS 2048
#define DDIM 1024
#define HH 16
#define RR (BB*SS)          /* 8192 rows */

// ---------------- scratch (static device arrays; no cudaMalloc) -------------
__device__ float g_qkv[(size_t)RR * 3 * DDIM];                   // 96 MB
__device__ __nv_bfloat16 g_ahi[(size_t)RR * DDIM];               // 16 MB
__device__ __nv_bfloat16 g_alo[(size_t)RR * DDIM];               // 16 MB
__device__ __nv_bfloat16 g_mhi[(size_t)RR * 4 * DDIM];           // 64 MB
__device__ __nv_bfloat16 g_mlo[(size_t)RR * 4 * DDIM];           // 64 MB
__device__ __nv_bfloat16 g_bhi[4u * 1024u * 1024u];              // 8 MB
__device__ __nv_bfloat16 g_blo[4u * 1024u * 1024u];              // 8 MB

// ---------------- helpers ----------------------------------------------------
__device__ __forceinline__ void cp_async16(uint32_t dst, const void* src) {
    asm volatile("cp.async.cg.shared.global [%0], [%1], 16;" :: "r"(dst), "l"(src));
}
__device__ __forceinline__ void cp_commit() {
    asm volatile("cp.async.commit_group;" ::: "memory");
}
template <int N> __device__ __forceinline__ void cp_wait() {
    asm volatile("cp.async.wait_group %0;" :: "n"(N) : "memory");
}
__device__ __forceinline__ void ldsm4(uint32_t &r0, uint32_t &r1, uint32_t &r2,
                                      uint32_t &r3, uint32_t addr) {
    asm volatile("ldmatrix.sync.aligned.m8n8.x4.shared.b16 {%0,%1,%2,%3}, [%4];"
        : "=r"(r0), "=r"(r1), "=r"(r2), "=r"(r3) : "r"(addr));
}
__device__ __forceinline__ void mma16816(float* d, uint32_t a0, uint32_t a1,
                                         uint32_t a2, uint32_t a3,
                                         uint32_t b0, uint32_t b1) {
    asm volatile(
        "mma.sync.aligned.m16n8k16.row.col.f32.bf16.bf16.f32 "
        "{%0,%1,%2,%3}, {%4,%5,%6,%7}, {%8,%9}, {%0,%1,%2,%3};"
        : "+f"(d[0]), "+f"(d[1]), "+f"(d[2]), "+f"(d[3])
        : "r"(a0), "r"(a1), "r"(a2), "r"(a3), "r"(b0), "r"(b1));
}
__device__ __forceinline__ void split2(float x, float y,
                                       __nv_bfloat162 &h2, __nv_bfloat162 &l2) {
    __nv_bfloat16 hx = __float2bfloat16(x), hy = __float2bfloat16(y);
    h2 = __halves2bfloat162(hx, hy);
    l2 = __halves2bfloat162(__float2bfloat16(x - __bfloat162float(hx)),
                            __float2bfloat16(y - __bfloat162float(hy)));
}
__device__ __forceinline__ float gelu_f(float v) {
    const float c = 0.7978845608028654f;
    float t = tanhf(c * (v + 0.044715f * v * v * v));
    return v * 0.5f * (1.0f + t);
}

// ---------------- LayerNorm fused with bf16 hi/lo split ----------------------
__global__ __launch_bounds__(256) void ln_split_kernel(
    const float* __restrict__ x, const float* __restrict__ gw,
    const float* __restrict__ sw, __nv_bfloat16* __restrict__ hi,
    __nv_bfloat16* __restrict__ lo)
{
    int row = blockIdx.x;
    int tid = threadIdx.x;
    const float4* xr = (const float4*)(x + (size_t)row * DDIM);
    float4 xv = xr[tid];
    float sum = xv.x + xv.y + xv.z + xv.w;
    float sq  = xv.x*xv.x + xv.y*xv.y + xv.z*xv.z + xv.w*xv.w;
    #pragma unroll
    for (int o = 16; o > 0; o >>= 1) {
        sum += __shfl_down_sync(0xffffffffu, sum, o);
        sq  += __shfl_down_sync(0xffffffffu, sq,  o);
    }
    __shared__ float rs[8], rq[8], bmean, brstd;
    int wid = tid >> 5, lid = tid & 31;
    if (lid == 0) { rs[wid] = sum; rq[wid] = sq; }
    __syncthreads();
    if (wid == 0) {
        float s2 = (lid < 8) ? rs[lid] : 0.f;
        float q2 = (lid < 8) ? rq[lid] : 0.f;
        #pragma unroll
        for (int o = 4; o > 0; o >>= 1) {
            s2 += __shfl_down_sync(0xffffffffu, s2, o);
            q2 += __shfl_down_sync(0xffffffffu, q2, o);
        }
        if (lid == 0) {
            float mean = s2 * (1.0f / DDIM);
            float var  = q2 * (1.0f / DDIM) - mean * mean;
            bmean = mean; brstd = rsqrtf(var + 1e-5f);
        }
    }
    __syncthreads();
    float mean = bmean, rstd = brstd;
    float4 gv = ((const float4*)gw)[tid];
    float4 sv = ((const float4*)sw)[tid];
    float o0 = gv.x * ((xv.x - mean) * rstd) + sv.x;
    float o1 = gv.y * ((xv.y - mean) * rstd) + sv.y;
    float o2 = gv.z * ((xv.z - mean) * rstd) + sv.z;
    float o3 = gv.w * ((xv.w - mean) * rstd) + sv.w;
    __nv_bfloat162 h2a, l2a, h2b, l2b;
    split2(o0, o1, h2a, l2a);
    split2(o2, o3, h2b, l2b);
    __nv_bfloat162* hp = (__nv_bfloat162*)(hi + (size_t)row * DDIM);
    __nv_bfloat162* lp = (__nv_bfloat162*)(lo + (size_t)row * DDIM);
    hp[2*tid] = h2a; hp[2*tid+1] = h2b;
    lp[2*tid] = l2a; lp[2*tid+1] = l2b;
}

// ---------------- weight transpose + split: W[K,N] -> out[N,K] hi/lo --------
__global__ __launch_bounds__(256) void cvt_t_kernel(
    const float* __restrict__ W, __nv_bfloat16* __restrict__ hi,
    __nv_bfloat16* __restrict__ lo, int K, int N)
{
    __shared__ float t[32][33];
    int n0 = blockIdx.x * 32, k0 = blockIdx.y * 32;
    int tx = threadIdx.x & 31, ty = threadIdx.x >> 5;   // 32 x 8
    #pragma unroll
    for (int i = 0; i < 4; i++)
        t[ty + 8*i][tx] = W[(size_t)(k0 + ty + 8*i) * N + n0 + tx];
    __syncthreads();
    #pragma unroll
    for (int i = 0; i < 4; i++) {
        float v = t[tx][ty + 8*i];
        size_t o = (size_t)(n0 + ty + 8*i) * K + k0 + tx;
        __nv_bfloat16 h = __float2bfloat16(v);
        hi[o] = h;
        lo[o] = __float2bfloat16(v - __bfloat162float(h));
    }
}

// ---------------- warp-MMA bf16 GEMM -----------------------------------------
// C[M,N] = Ahi*Bhi + Ahi*Blo + Alo*Bhi (3 split passes folded into K loop)
// A: [M,K] bf16 row-major; B: [N,K] bf16 row-major (W^T).
// 128x128 tile, BK=32, 8 warps (64x32 each), 4-stage cp.async.
#define TG_SMEM (4 * 16384)

template <bool BIAS, bool GELU, bool RES, bool SPL>
__global__ __launch_bounds__(256, 2) void tgemm_kernel(
    const __nv_bfloat16* __restrict__ Ahi, const __nv_bfloat16* __restrict__ Alo,
    const __nv_bfloat16* __restrict__ Bhi, const __nv_bfloat16* __restrict__ Blo,
    const float* __restrict__ bias, const float* __restrict__ res,
    float* __restrict__ C, __nv_bfloat16* __restrict__ Chi,
    __nv_bfloat16* __restrict__ Clo, int M, int N, int K)
{
    extern __shared__ char smem[];
    uint32_t sb = (uint32_t)__cvta_generic_to_shared(smem);
    int tid = threadIdx.x, lane = tid & 31, wid = tid >> 5;
    int wm = wid & 1, wn = wid >> 1;
    size_t row0 = (size_t)blockIdx.y * 128;
    size_t col0 = (size_t)blockIdx.x * 128;
    const int kc = K >> 5;
    const int NC = 3 * kc;

    float acc[4][4][4];
    #pragma unroll
    for (int i = 0; i < 4; i++)
        #pragma unroll
        for (int j = 0; j < 4; j++)
            #pragma unroll
            for (int r = 0; r < 4; r++) acc[i][j][r] = 0.f;

    // ldmatrix lane constants (swizzle xor invariant under +16 rows)
    int rowA = wm * 64 + (lane & 15);
    uint32_t xvA = (uint32_t)((rowA >> 1) & 3);
    int hiA = lane >> 4;
    int nrow = wn * 32 + (lane & 7) + ((lane & 16) >> 1);
    uint32_t xvB = (uint32_t)((nrow >> 1) & 3);
    int hiB = (lane >> 3) & 1;

    auto load_chunk = [&](int c) {
        if (c < NC) {
            int p = c / kc;
            int k0 = (c - p * kc) << 5;
            const __nv_bfloat16* Ag = (p == 2) ? Alo : Ahi;
            const __nv_bfloat16* Bg = (p == 1) ? Blo : Bhi;
            uint32_t sA = sb + (c & 3) * 16384;
            uint32_t sB = sA + 8192;
            #pragma unroll
            for (int i = 0; i < 2; i++) {
                int idx = i * 256 + tid;
                int r = idx >> 2, ck = idx & 3;
                uint32_t off = (uint32_t)(r * 64 + ((ck ^ ((r >> 1) & 3)) << 4));
                cp_async16(sA + off, Ag + (row0 + r) * K + k0 + ck * 8);
                cp_async16(sB + off, Bg + (col0 + r) * K + k0 + ck * 8);
            }
        }
        cp_commit();
    };

    load_chunk(0); load_chunk(1); load_chunk(2);

    for (int c = 0; c < NC; c++) {
        cp_wait<2>();
        __syncthreads();                 // stage c readable; stage (c-1)&3 reusable
        load_chunk(c + 3);
        uint32_t sA = sb + (c & 3) * 16384;
        uint32_t sB = sA + 8192;
        #pragma unroll
        for (int ks = 0; ks < 2; ks++) {
            uint32_t a[4][4], bf[4][2];
            uint32_t ckA = ((uint32_t)(2*ks + hiA)) ^ xvA;
            uint32_t ckB = ((uint32_t)(2*ks + hiB)) ^ xvB;
            #pragma unroll
            for (int mt = 0; mt < 4; mt++)
                ldsm4(a[mt][0], a[mt][1], a[mt][2], a[mt][3],
                      sA + (uint32_t)((rowA + mt*16) * 64) + (ckA << 4));
            #pragma unroll
            for (int np = 0; np < 2; np++)
                ldsm4(bf[np*2][0], bf[np*2][1], bf[np*2+1][0], bf[np*2+1][1],
                      sB + (uint32_t)((nrow + np*16) * 64) + (ckB << 4));
            #pragma unroll
            for (int mt = 0; mt < 4; mt++)
                #pragma unroll
                for (int nt = 0; nt < 4; nt++)
                    mma16816(acc[mt][nt], a[mt][0], a[mt][1], a[mt][2], a[mt][3],
                             bf[nt][0], bf[nt][1]);
        }
    }

    // ---------------- epilogue ----------------
    size_t rbase = row0 + wm*64 + (lane >> 2);
    size_t cbase = col0 + wn*32 + (lane & 3) * 2;
    #pragma unroll
    for (int mt = 0; mt < 4; mt++) {
        #pragma unroll
        for (int h = 0; h < 2; h++) {
            size_t r = rbase + mt*16 + h*8;
            #pragma unroll
            for (int nt = 0; nt < 4; nt++) {
                size_t cidx = cbase + nt*8;
                float v0 = acc[mt][nt][2*h], v1 = acc[mt][nt][2*h+1];
                if (BIAS) {
                    float2 bv = *(const float2*)(bias + cidx);
                    v0 += bv.x; v1 += bv.y;
                }
                if (GELU) { v0 = gelu_f(v0); v1 = gelu_f(v1); }
                if (RES) {
                    float2 rv = *(const float2*)(res + r * N + cidx);
                    v0 += rv.x; v1 += rv.y;
                }
                if (SPL) {
                    __nv_bfloat162 h2, l2;
                    split2(v0, v1, h2, l2);
                    *(__nv_bfloat162*)(Chi + r * N + cidx) = h2;
                    *(__nv_bfloat162*)(Clo + r * N + cidx) = l2;
                } else {
                    float2 o; o.x = v0; o.y = v1;
                    *(float2*)(C + r * N + cidx) = o;
                }
            }
        }
    }
}

// ---------------- flash attention (fp32 in, bf16 hi/lo split out) ------------
__global__ __launch_bounds__(64) void attn_kernel(
    const float* __restrict__ qkv, __nv_bfloat16* __restrict__ chi,
    __nv_bfloat16* __restrict__ clo)
{
    int qt = blockIdx.x, h = blockIdx.y, b = blockIdx.z;
    int t  = threadIdx.x;
    int qrow = qt * 64 + t;

    __shared__ float Ks[32][64];
    __shared__ float Vs[32][64];
    __shared__ float Ss[64][33];

    float q[64], acc[64];
    const float scale = 0.125f;
    size_t qbase = ((size_t)b * SS + qrow) * 3 * DDIM + (size_t)h * 64;
    #pragma unroll
    for (int d = 0; d < 64; d += 4) {
        float4 qv = *(const float4*)(qkv + qbase + d);
        q[d+0] = qv.x * scale; q[d+1] = qv.y * scale;
        q[d+2] = qv.z * scale; q[d+3] = qv.w * scale;
        acc[d+0] = 0.f; acc[d+1] = 0.f; acc[d+2] = 0.f; acc[d+3] = 0.f;
    }

    float m = -INFINITY, l = 0.f;
    int ntiles = (qt * 64 + 63) / 32 + 1;

    for (int kt = 0; kt < ntiles; kt++) {
        int kbase = kt * 32;
        __syncthreads();
        #pragma unroll
        for (int i = 0; i < 8; i++) {
            int fi = t + 64 * i;
            int r  = fi >> 4;
            int c4 = fi & 15;
            size_t kr = ((size_t)b * SS + kbase + r) * 3 * DDIM + DDIM + (size_t)h * 64;
            *(float4*)&Ks[r][c4*4] = *(const float4*)(qkv + kr + c4 * 4);
            *(float4*)&Vs[r][c4*4] = *(const float4*)(qkv + kr + DDIM + c4 * 4);
        }
        __syncthreads();

        int jmax = qrow - kbase + 1;
        if (jmax > 32) jmax = 32;
        float tmax = -INFINITY;
        #pragma unroll 4
        for (int j = 0; j < 32; j++) {
            float s = 0.f;
            const float4* kr4 = (const float4*)Ks[j];
            #pragma unroll
            for (int d4 = 0; d4 < 16; d4++) {
                float4 kv = kr4[d4];
                s += q[4*d4+0]*kv.x + q[4*d4+1]*kv.y + q[4*d4+2]*kv.z + q[4*d4+3]*kv.w;
            }
            if (j >= jmax) s = -INFINITY;
            Ss[t][j] = s;
            tmax = fmaxf(tmax, s);
        }
        float mnew = fmaxf(m, tmax);
        float corr = expf(m - mnew);
        l *= corr;
        #pragma unroll
        for (int d = 0; d < 64; d++) acc[d] *= corr;
        #pragma unroll 2
        for (int j = 0; j < 32; j++) {
            float p = expf(Ss[t][j] - mnew);
            l += p;
            const float4* vr4 = (const float4*)Vs[j];
            #pragma unroll
            for (int d4 = 0; d4 < 16; d4++) {
                float4 vv = vr4[d4];
                acc[4*d4+0] += p * vv.x; acc[4*d4+1] += p * vv.y;
                acc[4*d4+2] += p * vv.z; acc[4*d4+3] += p * vv.w;
            }
        }
        m = mnew;
    }

    float inv = 1.f / l;
    size_t obase = ((size_t)b * SS + qrow) * DDIM + (size_t)h * 64;
    #pragma unroll
    for (int d = 0; d < 64; d += 2) {
        __nv_bfloat162 h2, l2;
        split2(acc[d] * inv, acc[d+1] * inv, h2, l2);
        *(__nv_bfloat162*)(chi + obase + d) = h2;
        *(__nv_bfloat162*)(clo + obase + d) = l2;
    }
}

// ---------------- host launch ------------------------------------------------
extern "C" void kernel_launch(void* const* d_in, const int* in_sizes, int n_in,
                              void* d_out, int out_size)
{
    const float* x    = (const float*)d_in[0];
    const float* Wqkv = (const float*)d_in[1];
    const float* Wout = (const float*)d_in[2];
    const float* bout = (const float*)d_in[3];
    const float* W1   = (const float*)d_in[4];
    const float* b1   = (const float*)d_in[5];
    const float* W2   = (const float*)d_in[6];
    const float* b2   = (const float*)d_in[7];
    const float* g1   = (const float*)d_in[8];
    const float* s1   = (const float*)d_in[9];
    const float* g2   = (const float*)d_in[10];
    const float* s2   = (const float*)d_in[11];
    float* out = (float*)d_out;

    float* pqkv;
    __nv_bfloat16 *pahi, *palo, *pmhi, *pmlo, *pbhi, *pblo;
    cudaGetSymbolAddress((void**)&pqkv, g_qkv);
    cudaGetSymbolAddress((void**)&pahi, g_ahi);
    cudaGetSymbolAddress((void**)&palo, g_alo);
    cudaGetSymbolAddress((void**)&pmhi, g_mhi);
    cudaGetSymbolAddress((void**)&pmlo, g_mlo);
    cudaGetSymbolAddress((void**)&pbhi, g_bhi);
    cudaGetSymbolAddress((void**)&pblo, g_blo);

    cudaFuncSetAttribute(tgemm_kernel<false,false,false,false>,
                         cudaFuncAttributeMaxDynamicSharedMemorySize, TG_SMEM);
    cudaFuncSetAttribute(tgemm_kernel<true,false,true,false>,
                         cudaFuncAttributeMaxDynamicSharedMemorySize, TG_SMEM);
    cudaFuncSetAttribute(tgemm_kernel<true,true,false,true>,
                         cudaFuncAttributeMaxDynamicSharedMemorySize, TG_SMEM);

    // 1. LN1 -> split(h)
    ln_split_kernel<<<RR, 256>>>(x, g1, s1, pahi, palo);
    // 2. qkv = h @ Wqkv
    cvt_t_kernel<<<dim3(3*DDIM/32, DDIM/32), 256>>>(Wqkv, pbhi, pblo, DDIM, 3*DDIM);
    tgemm_kernel<false,false,false,false><<<dim3(3*DDIM/128, RR/128), 256, TG_SMEM>>>(
        pahi, palo, pbhi, pblo, nullptr, nullptr, pqkv, nullptr, nullptr,
        RR, 3*DDIM, DDIM);
    // 3. attention -> split(ctx)
    attn_kernel<<<dim3(SS/64, HH, BB), 64>>>(pqkv, pahi, palo);
    // 4. out = x + ctx @ Wout + bout
    cvt_t_kernel<<<dim3(DDIM/32, DDIM/32), 256>>>(Wout, pbhi, pblo, DDIM, DDIM);
    tgemm_kernel<true,false,true,false><<<dim3(DDIM/128, RR/128), 256, TG_SMEM>>>(
        pahi, palo, pbhi, pblo, bout, x, out, nullptr, nullptr,
        RR, DDIM, DDIM);
    // 5. LN2 -> split(h)
    ln_split_kernel<<<RR, 256>>>(out, g2, s2, pahi, palo);
    // 6. mid = gelu(h @ W1 + b1) -> split(mid)
    cvt_t_kernel<<<dim3(4*DDIM/32, DDIM/32), 256>>>(W1, pbhi, pblo, DDIM, 4*DDIM);
    tgemm_kernel<true,true,false,true><<<dim3(4*DDIM/128, RR/128), 256, TG_SMEM>>>(
        pahi, palo, pbhi, pblo, b1, nullptr, nullptr, pmhi, pmlo,
        RR, 4*DDIM, DDIM);
    // 7. out = out + mid @ W2 + b2
    cvt_t_kernel<<<dim3(DDIM/32, 4*DDIM/32), 256>>>(W2, pbhi, pblo, 4*DDIM, DDIM);
    tgemm_kernel<true,false,true,false><<<dim3(DDIM/128, RR/128), 256, TG_SMEM>>>(
        pmhi, pmlo, pbhi, pblo, b2, out, out, nullptr, nullptr,
        RR, DDIM, 4*DDIM);
}

// round 5
// speedup vs baseline: 3.4191x; 2.1512x over previous
#include <cuda_runtime.h>
#include <cuda_bf16.h>
#include <math.h>
#include <stdint.h>

#define BB 4
#define SS 2048
#define DDIM 1024
#define HH 16
#define RR (BB*SS)          /* 8192 rows */

// ---------------- scratch (static device arrays; no cudaMalloc) -------------
__device__ __nv_bfloat16 g_ahi[(size_t)RR * DDIM];               // 16 MB
__device__ __nv_bfloat16 g_alo[(size_t)RR * DDIM];               // 16 MB
__device__ __nv_bfloat16 g_mhi[(size_t)RR * 4 * DDIM];           // 64 MB (also QKV)
__device__ __nv_bfloat16 g_mlo[(size_t)RR * 4 * DDIM];           // 64 MB
__device__ __nv_bfloat16 g_bhi[4u * 1024u * 1024u];              // 8 MB
__device__ __nv_bfloat16 g_blo[4u * 1024u * 1024u];              // 8 MB

// ---------------- helpers ----------------------------------------------------
#define SWZ(o) ((uint32_t)(o) ^ (((uint32_t)(o) >> 3) & 0x70u))

__device__ __forceinline__ void cp_async16(uint32_t dst, const void* src) {
    asm volatile("cp.async.cg.shared.global [%0], [%1], 16;" :: "r"(dst), "l"(src));
}
__device__ __forceinline__ void cp_commit() {
    asm volatile("cp.async.commit_group;" ::: "memory");
}
template <int N> __device__ __forceinline__ void cp_wait() {
    asm volatile("cp.async.wait_group %0;" :: "n"(N) : "memory");
}
__device__ __forceinline__ void ldsm4(uint32_t &r0, uint32_t &r1, uint32_t &r2,
                                      uint32_t &r3, uint32_t addr) {
    asm volatile("ldmatrix.sync.aligned.m8n8.x4.shared.b16 {%0,%1,%2,%3}, [%4];"
        : "=r"(r0), "=r"(r1), "=r"(r2), "=r"(r3) : "r"(addr));
}
__device__ __forceinline__ void ldsm4t(uint32_t &r0, uint32_t &r1, uint32_t &r2,
                                       uint32_t &r3, uint32_t addr) {
    asm volatile("ldmatrix.sync.aligned.m8n8.x4.trans.shared.b16 {%0,%1,%2,%3}, [%4];"
        : "=r"(r0), "=r"(r1), "=r"(r2), "=r"(r3) : "r"(addr));
}
__device__ __forceinline__ void mma16816(float* d, uint32_t a0, uint32_t a1,
                                         uint32_t a2, uint32_t a3,
                                         uint32_t b0, uint32_t b1) {
    asm volatile(
        "mma.sync.aligned.m16n8k16.row.col.f32.bf16.bf16.f32 "
        "{%0,%1,%2,%3}, {%4,%5,%6,%7}, {%8,%9}, {%0,%1,%2,%3};"
        : "+f"(d[0]), "+f"(d[1]), "+f"(d[2]), "+f"(d[3])
        : "r"(a0), "r"(a1), "r"(a2), "r"(a3), "r"(b0), "r"(b1));
}
__device__ __forceinline__ void split2(float x, float y,
                                       __nv_bfloat162 &h2, __nv_bfloat162 &l2) {
    __nv_bfloat16 hx = __float2bfloat16(x), hy = __float2bfloat16(y);
    h2 = __halves2bfloat162(hx, hy);
    l2 = __halves2bfloat162(__float2bfloat16(x - __bfloat162float(hx)),
                            __float2bfloat16(y - __bfloat162float(hy)));
}
__device__ __forceinline__ uint32_t packbf(float x, float y) {
    __nv_bfloat162 t = __halves2bfloat162(__float2bfloat16(x), __float2bfloat16(y));
    return *(uint32_t*)&t;
}
__device__ __forceinline__ float gelu_f(float v) {
    const float c = 0.7978845608028654f;
    float t = tanhf(c * (v + 0.044715f * v * v * v));
    return v * 0.5f * (1.0f + t);
}

// ---------------- LayerNorm fused with bf16 hi/lo split ----------------------
__global__ __launch_bounds__(256) void ln_split_kernel(
    const float* __restrict__ x, const float* __restrict__ gw,
    const float* __restrict__ sw, __nv_bfloat16* __restrict__ hi,
    __nv_bfloat16* __restrict__ lo)
{
    int row = blockIdx.x;
    int tid = threadIdx.x;
    const float4* xr = (const float4*)(x + (size_t)row * DDIM);
    float4 xv = xr[tid];
    float sum = xv.x + xv.y + xv.z + xv.w;
    float sq  = xv.x*xv.x + xv.y*xv.y + xv.z*xv.z + xv.w*xv.w;
    #pragma unroll
    for (int o = 16; o > 0; o >>= 1) {
        sum += __shfl_down_sync(0xffffffffu, sum, o);
        sq  += __shfl_down_sync(0xffffffffu, sq,  o);
    }
    __shared__ float rs[8], rq[8], bmean, brstd;
    int wid = tid >> 5, lid = tid & 31;
    if (lid == 0) { rs[wid] = sum; rq[wid] = sq; }
    __syncthreads();
    if (wid == 0) {
        float s2 = (lid < 8) ? rs[lid] : 0.f;
        float q2 = (lid < 8) ? rq[lid] : 0.f;
        #pragma unroll
        for (int o = 4; o > 0; o >>= 1) {
            s2 += __shfl_down_sync(0xffffffffu, s2, o);
            q2 += __shfl_down_sync(0xffffffffu, q2, o);
        }
        if (lid == 0) {
            float mean = s2 * (1.0f / DDIM);
            float var  = q2 * (1.0f / DDIM) - mean * mean;
            bmean = mean; brstd = rsqrtf(var + 1e-5f);
        }
    }
    __syncthreads();
    float mean = bmean, rstd = brstd;
    float4 gv = ((const float4*)gw)[tid];
    float4 sv = ((const float4*)sw)[tid];
    float o0 = gv.x * ((xv.x - mean) * rstd) + sv.x;
    float o1 = gv.y * ((xv.y - mean) * rstd) + sv.y;
    float o2 = gv.z * ((xv.z - mean) * rstd) + sv.z;
    float o3 = gv.w * ((xv.w - mean) * rstd) + sv.w;
    __nv_bfloat162 h2a, l2a, h2b, l2b;
    split2(o0, o1, h2a, l2a);
    split2(o2, o3, h2b, l2b);
    __nv_bfloat162* hp = (__nv_bfloat162*)(hi + (size_t)row * DDIM);
    __nv_bfloat162* lp = (__nv_bfloat162*)(lo + (size_t)row * DDIM);
    hp[2*tid] = h2a; hp[2*tid+1] = h2b;
    lp[2*tid] = l2a; lp[2*tid+1] = l2b;
}

// ---------------- weight transpose + split: W[K,N] -> out[N,K] hi/lo --------
__global__ __launch_bounds__(256) void cvt_t_kernel(
    const float* __restrict__ W, __nv_bfloat16* __restrict__ hi,
    __nv_bfloat16* __restrict__ lo, int K, int N)
{
    __shared__ float t[32][33];
    int n0 = blockIdx.x * 32, k0 = blockIdx.y * 32;
    int tx = threadIdx.x & 31, ty = threadIdx.x >> 5;   // 32 x 8
    #pragma unroll
    for (int i = 0; i < 4; i++)
        t[ty + 8*i][tx] = W[(size_t)(k0 + ty + 8*i) * N + n0 + tx];
    __syncthreads();
    #pragma unroll
    for (int i = 0; i < 4; i++) {
        float v = t[tx][ty + 8*i];
        size_t o = (size_t)(n0 + ty + 8*i) * K + k0 + tx;
        __nv_bfloat16 h = __float2bfloat16(v);
        hi[o] = h;
        lo[o] = __float2bfloat16(v - __bfloat162float(h));
    }
}

// ---------------- warp-MMA bf16 GEMM -----------------------------------------
// C[M,N] = Ahi*Bhi + Ahi*Blo + Alo*Bhi (3 split passes folded into K loop)
// A: [M,K] bf16 row-major; B: [N,K] bf16 row-major (W^T).
// 128x128 tile, BK=32, 8 warps (64x32 each), 4-stage cp.async.
#define TG_SMEM (4 * 16384)

template <bool BIAS, bool GELU, bool RES, bool SPL, bool QKV>
__global__ __launch_bounds__(256, 2) void tgemm_kernel(
    const __nv_bfloat16* __restrict__ Ahi, const __nv_bfloat16* __restrict__ Alo,
    const __nv_bfloat16* __restrict__ Bhi, const __nv_bfloat16* __restrict__ Blo,
    const float* __restrict__ bias, const float* __restrict__ res,
    float* __restrict__ C, __nv_bfloat16* __restrict__ Chi,
    __nv_bfloat16* __restrict__ Clo, int M, int N, int K)
{
    extern __shared__ char smem[];
    uint32_t sb = (uint32_t)__cvta_generic_to_shared(smem);
    int tid = threadIdx.x, lane = tid & 31, wid = tid >> 5;
    int wm = wid & 1, wn = wid >> 1;
    size_t row0 = (size_t)blockIdx.y * 128;
    size_t col0 = (size_t)blockIdx.x * 128;
    const int kc = K >> 5;
    const int NC = 3 * kc;

    float acc[4][4][4];
    #pragma unroll
    for (int i = 0; i < 4; i++)
        #pragma unroll
        for (int j = 0; j < 4; j++)
            #pragma unroll
            for (int r = 0; r < 4; r++) acc[i][j][r] = 0.f;

    int rowA = wm * 64 + (lane & 15);
    uint32_t xvA = (uint32_t)((rowA >> 1) & 3);
    int hiA = lane >> 4;
    int nrow = wn * 32 + (lane & 7) + ((lane & 16) >> 1);
    uint32_t xvB = (uint32_t)((nrow >> 1) & 3);
    int hiB = (lane >> 3) & 1;

    auto load_chunk = [&](int c) {
        if (c < NC) {
            int p = c / kc;
            int k0 = (c - p * kc) << 5;
            const __nv_bfloat16* Ag = (p == 2) ? Alo : Ahi;
            const __nv_bfloat16* Bg = (p == 1) ? Blo : Bhi;
            uint32_t sA = sb + (c & 3) * 16384;
            uint32_t sB = sA + 8192;
            #pragma unroll
            for (int i = 0; i < 2; i++) {
                int idx = i * 256 + tid;
                int r = idx >> 2, ck = idx & 3;
                uint32_t off = (uint32_t)(r * 64 + ((ck ^ ((r >> 1) & 3)) << 4));
                cp_async16(sA + off, Ag + (row0 + r) * K + k0 + ck * 8);
                cp_async16(sB + off, Bg + (col0 + r) * K + k0 + ck * 8);
            }
        }
        cp_commit();
    };

    load_chunk(0); load_chunk(1); load_chunk(2);

    for (int c = 0; c < NC; c++) {
        cp_wait<2>();
        __syncthreads();
        load_chunk(c + 3);
        uint32_t sA = sb + (c & 3) * 16384;
        uint32_t sB = sA + 8192;
        #pragma unroll
        for (int ks = 0; ks < 2; ks++) {
            uint32_t a[4][4], bf[4][2];
            uint32_t ckA = ((uint32_t)(2*ks + hiA)) ^ xvA;
            uint32_t ckB = ((uint32_t)(2*ks + hiB)) ^ xvB;
            #pragma unroll
            for (int mt = 0; mt < 4; mt++)
                ldsm4(a[mt][0], a[mt][1], a[mt][2], a[mt][3],
                      sA + (uint32_t)((rowA + mt*16) * 64) + (ckA << 4));
            #pragma unroll
            for (int np = 0; np < 2; np++)
                ldsm4(bf[np*2][0], bf[np*2][1], bf[np*2+1][0], bf[np*2+1][1],
                      sB + (uint32_t)((nrow + np*16) * 64) + (ckB << 4));
            #pragma unroll
            for (int mt = 0; mt < 4; mt++)
                #pragma unroll
                for (int nt = 0; nt < 4; nt++)
                    mma16816(acc[mt][nt], a[mt][0], a[mt][1], a[mt][2], a[mt][3],
                             bf[nt][0], bf[nt][1]);
        }
    }

    // ---------------- epilogue ----------------
    size_t rbase = row0 + wm*64 + (lane >> 2);
    size_t cbase = col0 + wn*32 + (lane & 3) * 2;
    #pragma unroll
    for (int mt = 0; mt < 4; mt++) {
        #pragma unroll
        for (int h = 0; h < 2; h++) {
            size_t r = rbase + mt*16 + h*8;
            #pragma unroll
            for (int nt = 0; nt < 4; nt++) {
                size_t cidx = cbase + nt*8;
                float v0 = acc[mt][nt][2*h], v1 = acc[mt][nt][2*h+1];
                if (BIAS) {
                    float2 bv = *(const float2*)(bias + cidx);
                    v0 += bv.x; v1 += bv.y;
                }
                if (GELU) { v0 = gelu_f(v0); v1 = gelu_f(v1); }
                if (RES) {
                    float2 rv = *(const float2*)(res + r * N + cidx);
                    v0 += rv.x; v1 += rv.y;
                }
                if (QKV) {
                    // N = 3*D: sec (q/k/v), head, d; row r -> (b, s)
                    int sec = (int)(cidx >> 10);
                    int hh  = ((int)cidx >> 6) & 15;
                    int d   = (int)cidx & 63;
                    int b   = (int)(r >> 11);
                    int s   = (int)(r & 2047);
                    if (sec == 0) { v0 *= 0.125f; v1 *= 0.125f; }
                    __nv_bfloat16* dst = Chi + (size_t)sec * RR * DDIM +
                        (((size_t)(b * HH + hh) * SS + s) << 6) + d;
                    *(__nv_bfloat162*)dst =
                        __halves2bfloat162(__float2bfloat16(v0), __float2bfloat16(v1));
                } else if (SPL) {
                    __nv_bfloat162 h2, l2;
                    split2(v0, v1, h2, l2);
                    *(__nv_bfloat162*)(Chi + r * N + cidx) = h2;
                    *(__nv_bfloat162*)(Clo + r * N + cidx) = l2;
                } else {
                    float2 o; o.x = v0; o.y = v1;
                    *(float2*)(C + r * N + cidx) = o;
                }
            }
        }
    }
}

// ---------------- tensor-core flash attention --------------------------------
// Q pre-scaled bf16 [B,H,S,64]; K,V bf16 [B,H,S,64]. 4 warps, 64 q rows/block.
// K/V chunks of 64 keys, double-buffered cp.async. Output: bf16 hi/lo ctx split.
__global__ __launch_bounds__(128) void attn_kernel(
    const __nv_bfloat16* __restrict__ Qg, const __nv_bfloat16* __restrict__ Kg,
    const __nv_bfloat16* __restrict__ Vg, __nv_bfloat16* __restrict__ chi,
    __nv_bfloat16* __restrict__ clo)
{
    __shared__ __align__(128) char smQ[64 * 128];
    __shared__ __align__(128) char smK[2][64 * 128];
    __shared__ __align__(128) char smV[2][64 * 128];

    int qt = blockIdx.x, h = blockIdx.y, b = blockIdx.z;
    int tid = threadIdx.x, lane = tid & 31, w = tid >> 5;

    size_t headbase = (size_t)(b * HH + h) * SS * 64;
    const __nv_bfloat16* Qh = Qg + headbase + (size_t)qt * 64 * 64;
    const __nv_bfloat16* Kh = Kg + headbase;
    const __nv_bfloat16* Vh = Vg + headbase;

    uint32_t sq  = (uint32_t)__cvta_generic_to_shared(smQ);
    uint32_t sk[2] = { (uint32_t)__cvta_generic_to_shared(smK[0]),
                       (uint32_t)__cvta_generic_to_shared(smK[1]) };
    uint32_t sv[2] = { (uint32_t)__cvta_generic_to_shared(smV[0]),
                       (uint32_t)__cvta_generic_to_shared(smV[1]) };

    // load Q tile (64 x 64 bf16 = 8KB): 512 x 16B, 4 per thread
    #pragma unroll
    for (int i = 0; i < 4; i++) {
        int idx = tid + 128 * i;
        int r = idx >> 3, c = idx & 7;
        cp_async16(sq + SWZ(r * 128 + c * 16), Qh + r * 64 + c * 8);
    }
    auto load_kv = [&](int kt) {
        int st = kt & 1;
        const __nv_bfloat16* Kc = Kh + (size_t)kt * 64 * 64;
        const __nv_bfloat16* Vc = Vh + (size_t)kt * 64 * 64;
        #pragma unroll
        for (int i = 0; i < 4; i++) {
            int idx = tid + 128 * i;
            int r = idx >> 3, c = idx & 7;
            uint32_t off = SWZ(r * 128 + c * 16);
            cp_async16(sk[st] + off, Kc + r * 64 + c * 8);
            cp_async16(sv[st] + off, Vc + r * 64 + c * 8);
        }
        cp_commit();
    };
    load_kv(0);
    cp_wait<0>();
    __syncthreads();

    // Q fragments: 4 ktiles (d), each 4 regs
    uint32_t qf[4][4];
    {
        int rowA = w * 16 + (lane & 15);
        #pragma unroll
        for (int dt = 0; dt < 4; dt++)
            ldsm4(qf[dt][0], qf[dt][1], qf[dt][2], qf[dt][3],
                  sq + SWZ(rowA * 128 + dt * 32 + (lane >> 4) * 16));
    }

    float acc[8][4];
    #pragma unroll
    for (int nt = 0; nt < 8; nt++)
        #pragma unroll
        for (int r = 0; r < 4; r++) acc[nt][r] = 0.f;
    float mrow[2] = { -INFINITY, -INFINITY };
    float lrow[2] = { 0.f, 0.f };

    for (int kt = 0; kt <= qt; kt++) {
        int st = kt & 1;
        if (kt < qt) load_kv(kt + 1);
        if (kt < qt) cp_wait<1>(); else cp_wait<0>();
        __syncthreads();

        // ---- S = Q K^T (64 keys) ----
        float s[8][4];
        #pragma unroll
        for (int nt = 0; nt < 8; nt++)
            #pragma unroll
            for (int r = 0; r < 4; r++) s[nt][r] = 0.f;
        int krow = (lane & 7) + ((lane & 16) >> 1);
        int khi  = (lane >> 3) & 1;
        #pragma unroll
        for (int dt = 0; dt < 4; dt++) {
            uint32_t kb[8][2];
            #pragma unroll
            for (int np = 0; np < 4; np++)
                ldsm4(kb[np*2][0], kb[np*2][1], kb[np*2+1][0], kb[np*2+1][1],
                      sk[st] + SWZ((np*16 + krow) * 128 + dt*32 + khi*16));
            #pragma unroll
            for (int nt = 0; nt < 8; nt++)
                mma16816(s[nt], qf[dt][0], qf[dt][1], qf[dt][2], qf[dt][3],
                         kb[nt][0], kb[nt][1]);
        }

        // ---- causal mask on diagonal chunk ----
        if (kt == qt) {
            #pragma unroll
            for (int nt = 0; nt < 8; nt++)
                #pragma unroll
                for (int r = 0; r < 4; r++) {
                    int qr = w*16 + (lane >> 2) + (r >> 1) * 8;
                    int kc = nt*8 + (lane & 3)*2 + (r & 1);
                    if (kc > qr) s[nt][r] = -INFINITY;
                }
        }

        // ---- online softmax ----
        #pragma unroll
        for (int hh = 0; hh < 2; hh++) {
            float mx = -INFINITY;
            #pragma unroll
            for (int nt = 0; nt < 8; nt++) {
                mx = fmaxf(mx, s[nt][2*hh]);
                mx = fmaxf(mx, s[nt][2*hh+1]);
            }
            mx = fmaxf(mx, __shfl_xor_sync(0xffffffffu, mx, 1));
            mx = fmaxf(mx, __shfl_xor_sync(0xffffffffu, mx, 2));
            float mnew = fmaxf(mrow[hh], mx);
            float corr = __expf(mrow[hh] - mnew);
            mrow[hh] = mnew;
            float psum = 0.f;
            #pragma unroll
            for (int nt = 0; nt < 8; nt++) {
                float p0 = __expf(s[nt][2*hh]   - mnew);
                float p1 = __expf(s[nt][2*hh+1] - mnew);
                s[nt][2*hh] = p0; s[nt][2*hh+1] = p1;
                psum += p0 + p1;
            }
            psum += __shfl_xor_sync(0xffffffffu, psum, 1);
            psum += __shfl_xor_sync(0xffffffffu, psum, 2);
            lrow[hh] = lrow[hh] * corr + psum;
            #pragma unroll
            for (int nt = 0; nt < 8; nt++) {
                acc[nt][2*hh]   *= corr;
                acc[nt][2*hh+1] *= corr;
            }
        }

        // ---- ctx += P V ----
        #pragma unroll
        for (int kt2 = 0; kt2 < 4; kt2++) {
            uint32_t a0 = packbf(s[2*kt2][0],   s[2*kt2][1]);
            uint32_t a1 = packbf(s[2*kt2][2],   s[2*kt2][3]);
            uint32_t a2 = packbf(s[2*kt2+1][0], s[2*kt2+1][1]);
            uint32_t a3 = packbf(s[2*kt2+1][2], s[2*kt2+1][3]);
            uint32_t vb[8][2];
            #pragma unroll
            for (int np = 0; np < 4; np++)
                ldsm4t(vb[np*2][0], vb[np*2][1], vb[np*2+1][0], vb[np*2+1][1],
                       sv[st] + SWZ((kt2*16 + (lane & 15)) * 128 + np*32 + (lane >> 4)*16));
            #pragma unroll
            for (int nt = 0; nt < 8; nt++)
                mma16816(acc[nt], a0, a1, a2, a3, vb[nt][0], vb[nt][1]);
        }
        __syncthreads();
    }

    // ---- normalize + write ctx as bf16 hi/lo split ----
    #pragma unroll
    for (int hh = 0; hh < 2; hh++) {
        float inv = 1.f / lrow[hh];
        int row = qt*64 + w*16 + (lane >> 2) + hh*8;
        size_t obase = ((size_t)(b * SS + row)) * DDIM + h * 64;
        #pragma unroll
        for (int nt = 0; nt < 8; nt++) {
            int d = nt*8 + (lane & 3)*2;
            __nv_bfloat162 h2, l2;
            split2(acc[nt][2*hh] * inv, acc[nt][2*hh+1] * inv, h2, l2);
            *(__nv_bfloat162*)(chi + obase + d) = h2;
            *(__nv_bfloat162*)(clo + obase + d) = l2;
        }
    }
}

// ---------------- host launch ------------------------------------------------
extern "C" void kernel_launch(void* const* d_in, const int* in_sizes, int n_in,
                              void* d_out, int out_size)
{
    const float* x    = (const float*)d_in[0];
    const float* Wqkv = (const float*)d_in[1];
    const float* Wout = (const float*)d_in[2];
    const float* bout = (const float*)d_in[3];
    const float* W1   = (const float*)d_in[4];
    const float* b1   = (const float*)d_in[5];
    const float* W2   = (const float*)d_in[6];
    const float* b2   = (const float*)d_in[7];
    const float* g1   = (const float*)d_in[8];
    const float* s1   = (const float*)d_in[9];
    const float* g2   = (const float*)d_in[10];
    const float* s2   = (const float*)d_in[11];
    float* out = (float*)d_out;

    __nv_bfloat16 *pahi, *palo, *pmhi, *pmlo, *pbhi, *pblo;
    cudaGetSymbolAddress((void**)&pahi, g_ahi);
    cudaGetSymbolAddress((void**)&palo, g_alo);
    cudaGetSymbolAddress((void**)&pmhi, g_mhi);
    cudaGetSymbolAddress((void**)&pmlo, g_mlo);
    cudaGetSymbolAddress((void**)&pbhi, g_bhi);
    cudaGetSymbolAddress((void**)&pblo, g_blo);

    __nv_bfloat16* pQ = pmhi;                          // [B,H,S,64]
    __nv_bfloat16* pK = pmhi + (size_t)RR * DDIM;
    __nv_bfloat16* pV = pmhi + (size_t)2 * RR * DDIM;

    cudaFuncSetAttribute(tgemm_kernel<false,false,false,false,true>,
                         cudaFuncAttributeMaxDynamicSharedMemorySize, TG_SMEM);
    cudaFuncSetAttribute(tgemm_kernel<true,false,true,false,false>,
                         cudaFuncAttributeMaxDynamicSharedMemorySize, TG_SMEM);
    cudaFuncSetAttribute(tgemm_kernel<true,true,false,true,false>,
                         cudaFuncAttributeMaxDynamicSharedMemorySize, TG_SMEM);

    // 1. LN1 -> split(h)
    ln_split_kernel<<<RR, 256>>>(x, g1, s1, pahi, palo);
    // 2. qkv = h @ Wqkv -> bf16 Q(scaled)/K/V head-major
    cvt_t_kernel<<<dim3(3*DDIM/32, DDIM/32), 256>>>(Wqkv, pbhi, pblo, DDIM, 3*DDIM);
    tgemm_kernel<false,false,false,false,true><<<dim3(3*DDIM/128, RR/128), 256, TG_SMEM>>>(
        pahi, palo, pbhi, pblo, nullptr, nullptr, nullptr, pQ, nullptr,
        RR, 3*DDIM, DDIM);
    // 3. attention -> split(ctx)
    attn_kernel<<<dim3(SS/64, HH, BB), 128>>>(pQ, pK, pV, pahi, palo);
    // 4. out = x + ctx @ Wout + bout
    cvt_t_kernel<<<dim3(DDIM/32, DDIM/32), 256>>>(Wout, pbhi, pblo, DDIM, DDIM);
    tgemm_kernel<true,false,true,false,false><<<dim3(DDIM/128, RR/128), 256, TG_SMEM>>>(
        pahi, palo, pbhi, pblo, bout, x, out, nullptr, nullptr,
        RR, DDIM, DDIM);
    // 5. LN2 -> split(h)
    ln_split_kernel<<<RR, 256>>>(out, g2, s2, pahi, palo);
    // 6. mid = gelu(h @ W1 + b1) -> split(mid)
    cvt_t_kernel<<<dim3(4*DDIM/32, DDIM/32), 256>>>(W1, pbhi, pblo, DDIM, 4*DDIM);
    tgemm_kernel<true,true,false,true,false><<<dim3(4*DDIM/128, RR/128), 256, TG_SMEM>>>(
        pahi, palo, pbhi, pblo, b1, nullptr, nullptr, pmhi, pmlo,
        RR, 4*DDIM, DDIM);
    // 7. out = out + mid @ W2 + b2
    cvt_t_kernel<<<dim3(DDIM/32, 4*DDIM/32), 256>>>(W2, pbhi, pblo, 4*DDIM, DDIM);
    tgemm_kernel<true,false,true,false,false><<<dim3(DDIM/128, RR/128), 256, TG_SMEM>>>(
        pmhi, pmlo, pbhi, pblo, b2, out, out, nullptr, nullptr,
        RR, DDIM, 4*DDIM);
}